// round 6
// baseline (speedup 1.0000x reference)
#include <cuda_runtime.h>
#include <cuda_bf16.h>
#include <math.h>
#include <stdint.h>

// ---------------------------------------------------------------- constants
#define B_    2
#define S_    2048
#define H_    32
#define D_    128
#define DIM_  4096
#define ADL_  10
#define MROWS (B_ * S_)
#define NELEM ((size_t)MROWS * DIM_)

// ---------------------------------------------------------------- scratch
__device__ float g_aK[ADL_ * DIM_];
__device__ float g_aV[ADL_ * DIM_];

// input splits
__device__ __nv_bfloat16 g_xh[NELEM],  g_xl[NELEM];
__device__ __nv_bfloat16 g_wqh[NELEM], g_wql[NELEM];
__device__ __nv_bfloat16 g_wkh[NELEM], g_wkl[NELEM];
__device__ __nv_bfloat16 g_wvh[NELEM], g_wvl[NELEM];
__device__ __nv_bfloat16 g_woh[NELEM], g_wol[NELEM];
// QKV outputs (roped, split)
__device__ __nv_bfloat16 g_qh[NELEM],  g_ql[NELEM];
__device__ __nv_bfloat16 g_kh[NELEM],  g_kl[NELEM];
__device__ __nv_bfloat16 g_vh[NELEM],  g_vl[NELEM];
// attention output (split)
__device__ __nv_bfloat16 g_oh[NELEM],  g_ol[NELEM];

// ---------------------------------------------------------------- PTX utils
__device__ __forceinline__ uint32_t smem_u32(const void* p) {
    uint32_t a;
    asm("{ .reg .u64 t; cvta.to.shared.u64 t, %1; cvt.u32.u64 %0, t; }"
        : "=r"(a) : "l"(p));
    return a;
}
#define CP_ASYNC16(dst, src) \
    asm volatile("cp.async.cg.shared.global [%0], [%1], 16;" \
                 :: "r"(dst), "l"(src) : "memory")
#define CP_COMMIT() asm volatile("cp.async.commit_group;" ::: "memory")
#define CP_WAIT(n)  asm volatile("cp.async.wait_group %0;" :: "n"(n) : "memory")

#define LDSM_X4(r0, r1, r2, r3, addr) \
    asm volatile("ldmatrix.sync.aligned.m8n8.x4.shared.b16 {%0,%1,%2,%3}, [%4];" \
                 : "=r"(r0), "=r"(r1), "=r"(r2), "=r"(r3) : "r"(addr))
#define LDSM_X4_T(r0, r1, r2, r3, addr) \
    asm volatile("ldmatrix.sync.aligned.m8n8.x4.trans.shared.b16 {%0,%1,%2,%3}, [%4];" \
                 : "=r"(r0), "=r"(r1), "=r"(r2), "=r"(r3) : "r"(addr))

#define MMA16816(c, a, b) \
    asm volatile("mma.sync.aligned.m16n8k16.row.col.f32.bf16.bf16.f32 " \
                 "{%0,%1,%2,%3}, {%4,%5,%6,%7}, {%8,%9}, {%0,%1,%2,%3};" \
                 : "+f"((c)[0]), "+f"((c)[1]), "+f"((c)[2]), "+f"((c)[3]) \
                 : "r"((a)[0]), "r"((a)[1]), "r"((a)[2]), "r"((a)[3]), \
                   "r"((b)[0]), "r"((b)[1]))

__device__ __forceinline__ uint32_t pack_bf16x2(float lo, float hi) {
    __nv_bfloat162 t = __floats2bfloat162_rn(lo, hi);
    return *(uint32_t*)&t;
}
__device__ __forceinline__ void split_store(__nv_bfloat16* Xh, __nv_bfloat16* Xl,
                                            size_t off, float v0, float v1) {
    __nv_bfloat16 h0 = __float2bfloat16(v0);
    __nv_bfloat16 h1 = __float2bfloat16(v1);
    __nv_bfloat16 l0 = __float2bfloat16(v0 - __bfloat162float(h0));
    __nv_bfloat16 l1 = __float2bfloat16(v1 - __bfloat162float(h1));
    *(__nv_bfloat162*)(Xh + off) = __nv_bfloat162(h0, h1);
    *(__nv_bfloat162*)(Xl + off) = __nv_bfloat162(l0, l1);
}

// ============================================================================
// GEMM core (bf16x3 HMMA, 128x128 CTA tile, BK=32, 4-stage cp.async)
// ============================================================================
#define GK_BK      32
#define GK_TILE_B  10240
#define GK_STAGE_B (4 * GK_TILE_B)
#define GK_STAGES  4
#define GK_SMEM    (GK_STAGES * GK_STAGE_B)
#define GK_NIT     (DIM_ / GK_BK)

__device__ __forceinline__ void gk_fill(uint32_t sbase,
    const __nv_bfloat16* __restrict__ Ah, const __nv_bfloat16* __restrict__ Al,
    const __nv_bfloat16* __restrict__ Bh, const __nv_bfloat16* __restrict__ Bl,
    int rowBase, int colBase, int k0)
{
    const int tid = threadIdx.x;
#pragma unroll
    for (int i = 0; i < 2; i++) {
        int idx = tid + i * 256;
        int row = idx >> 2;
        int cg  = (idx & 3) * 8;
        uint32_t doff = (uint32_t)(row * 80 + (idx & 3) * 16);
        size_t ga = (size_t)(rowBase + row) * DIM_ + k0 + cg;
        size_t gb = (size_t)(colBase + row) * DIM_ + k0 + cg;
        CP_ASYNC16(sbase + doff,                 Ah + ga);
        CP_ASYNC16(sbase + GK_TILE_B + doff,     Al + ga);
        CP_ASYNC16(sbase + 2 * GK_TILE_B + doff, Bh + gb);
        CP_ASYNC16(sbase + 3 * GK_TILE_B + doff, Bl + gb);
    }
}

// mainloop producing acc[4][4][4]; shared by both GEMM kernels
#define GK_MAINLOOP(Ah, Al, Bh, Bl)                                            \
    gk_fill(base,                  Ah, Al, Bh, Bl, rowBase, colBase, 0);       \
    CP_COMMIT();                                                               \
    gk_fill(base + GK_STAGE_B,     Ah, Al, Bh, Bl, rowBase, colBase, GK_BK);   \
    CP_COMMIT();                                                               \
    gk_fill(base + 2 * GK_STAGE_B, Ah, Al, Bh, Bl, rowBase, colBase, 2*GK_BK); \
    CP_COMMIT();                                                               \
    const uint32_t aRow = (uint32_t)(wm + (lane & 15));                        \
    const uint32_t bRow = (uint32_t)(wn + (lane & 15));                        \
    const uint32_t kHalf = (uint32_t)((lane >> 4) * 16);                       \
    for (int it = 0; it < GK_NIT; it++) {                                      \
        CP_WAIT(2);                                                            \
        __syncthreads();                                                       \
        if (it + 3 < GK_NIT)                                                   \
            gk_fill(base + (uint32_t)((it + 3) & 3) * GK_STAGE_B,              \
                    Ah, Al, Bh, Bl, rowBase, colBase, (it + 3) * GK_BK);       \
        CP_COMMIT();                                                           \
        const uint32_t sb = base + (uint32_t)(it & 3) * GK_STAGE_B;            \
        _Pragma("unroll")                                                      \
        for (int ks = 0; ks < 2; ks++) {                                       \
            const uint32_t kcol = (uint32_t)(ks * 32) + kHalf;                 \
            uint32_t ah[4][4], al[4][4], bh[4][2], bl[4][2];                   \
            _Pragma("unroll")                                                  \
            for (int mi = 0; mi < 4; mi++) {                                   \
                uint32_t off = (aRow + mi * 16) * 80 + kcol;                   \
                LDSM_X4(ah[mi][0], ah[mi][1], ah[mi][2], ah[mi][3], sb + off); \
                LDSM_X4(al[mi][0], al[mi][1], al[mi][2], al[mi][3],            \
                        sb + GK_TILE_B + off);                                 \
            }                                                                  \
            _Pragma("unroll")                                                  \
            for (int np = 0; np < 2; np++) {                                   \
                uint32_t off = (bRow + np * 16) * 80 + kcol;                   \
                uint32_t r0, r1, r2, r3;                                       \
                LDSM_X4(r0, r1, r2, r3, sb + 2 * GK_TILE_B + off);             \
                bh[2 * np][0] = r0; bh[2 * np][1] = r2;                        \
                bh[2 * np + 1][0] = r1; bh[2 * np + 1][1] = r3;                \
                LDSM_X4(r0, r1, r2, r3, sb + 3 * GK_TILE_B + off);             \
                bl[2 * np][0] = r0; bl[2 * np][1] = r2;                        \
                bl[2 * np + 1][0] = r1; bl[2 * np + 1][1] = r3;                \
            }                                                                  \
            _Pragma("unroll")                                                  \
            for (int mi = 0; mi < 4; mi++)                                     \
                _Pragma("unroll")                                              \
                for (int ni = 0; ni < 4; ni++) {                               \
                    MMA16816(acc[mi][ni], ah[mi], bh[ni]);                     \
                    MMA16816(acc[mi][ni], ah[mi], bl[ni]);                     \
                    MMA16816(acc[mi][ni], al[mi], bh[ni]);                     \
                }                                                              \
        }                                                                      \
    }

// --------- final output GEMM: fp32 C ---------
__global__ __launch_bounds__(256, 1)
void mma_gemm(const __nv_bfloat16* __restrict__ Ah, const __nv_bfloat16* __restrict__ Al,
              const __nv_bfloat16* __restrict__ Bh, const __nv_bfloat16* __restrict__ Bl,
              float* __restrict__ C)
{
    extern __shared__ char sm[];
    const uint32_t base = smem_u32(sm);
    const int lane = threadIdx.x & 31;
    const int wid  = threadIdx.x >> 5;
    const int rowBase = blockIdx.y * 128;
    const int colBase = blockIdx.x * 128;
    const int wm = (wid & 1) * 64;
    const int wn = (wid >> 1) * 32;

    float acc[4][4][4];
#pragma unroll
    for (int mi = 0; mi < 4; mi++)
#pragma unroll
        for (int ni = 0; ni < 4; ni++)
#pragma unroll
            for (int q = 0; q < 4; q++) acc[mi][ni][q] = 0.f;

    GK_MAINLOOP(Ah, Al, Bh, Bl)

    const int r0 = rowBase + wm + (lane >> 2);
    const int c0 = colBase + wn + (lane & 3) * 2;
#pragma unroll
    for (int mi = 0; mi < 4; mi++)
#pragma unroll
        for (int ni = 0; ni < 4; ni++) {
            float* p = C + (size_t)(r0 + mi * 16) * DIM_ + c0 + ni * 8;
            *(float2*)p = make_float2(acc[mi][ni][0], acc[mi][ni][1]);
            *(float2*)(p + 8 * DIM_) = make_float2(acc[mi][ni][2], acc[mi][ni][3]);
        }
}

// --------- QKV GEMM: z selects weights/output; rope fused for z<2 ---------
__global__ __launch_bounds__(256, 1)
void qkv_gemm(const __nv_bfloat16* __restrict__ Ah, const __nv_bfloat16* __restrict__ Al,
              const __nv_bfloat16* __restrict__ Bqh, const __nv_bfloat16* __restrict__ Bql,
              const __nv_bfloat16* __restrict__ Bkh, const __nv_bfloat16* __restrict__ Bkl,
              const __nv_bfloat16* __restrict__ Bvh, const __nv_bfloat16* __restrict__ Bvl,
              __nv_bfloat16* __restrict__ Qh, __nv_bfloat16* __restrict__ Ql,
              __nv_bfloat16* __restrict__ Kh, __nv_bfloat16* __restrict__ Kl,
              __nv_bfloat16* __restrict__ Vh, __nv_bfloat16* __restrict__ Vl,
              const float* __restrict__ fcos, const float* __restrict__ fsin)
{
    extern __shared__ char sm[];
    const uint32_t base = smem_u32(sm);
    const int lane = threadIdx.x & 31;
    const int wid  = threadIdx.x >> 5;
    const int rowBase = blockIdx.y * 128;
    const int colBase = blockIdx.x * 128;
    const int wm = (wid & 1) * 64;
    const int wn = (wid >> 1) * 32;
    const int z = blockIdx.z;

    const __nv_bfloat16* Bh = (z == 0) ? Bqh : (z == 1) ? Bkh : Bvh;
    const __nv_bfloat16* Bl = (z == 0) ? Bql : (z == 1) ? Bkl : Bvl;
    __nv_bfloat16* Xh = (z == 0) ? Qh : (z == 1) ? Kh : Vh;
    __nv_bfloat16* Xl = (z == 0) ? Ql : (z == 1) ? Kl : Vl;
    const bool dorope = (z < 2);

    float acc[4][4][4];
#pragma unroll
    for (int mi = 0; mi < 4; mi++)
#pragma unroll
        for (int ni = 0; ni < 4; ni++)
#pragma unroll
            for (int q = 0; q < 4; q++) acc[mi][ni][q] = 0.f;

    GK_MAINLOOP(Ah, Al, Bh, Bl)

    const int r0 = rowBase + wm + (lane >> 2);
    const int c0 = colBase + wn + (lane & 3) * 2;
#pragma unroll
    for (int mi = 0; mi < 4; mi++) {
        int r  = r0 + mi * 16;
        int s1 = r & (S_ - 1);
        int s2 = (r + 8) & (S_ - 1);
#pragma unroll
        for (int ni = 0; ni < 4; ni++) {
            int c = c0 + ni * 8;
            float v0 = acc[mi][ni][0], v1 = acc[mi][ni][1];
            float v2 = acc[mi][ni][2], v3 = acc[mi][ni][3];
            if (dorope) {
                int i = (c & (D_ - 1)) >> 1;
                float c1 = fcos[s1 * 64 + i], n1 = fsin[s1 * 64 + i];
                float c2 = fcos[s2 * 64 + i], n2 = fsin[s2 * 64 + i];
                float t;
                t = v0 * c1 - v1 * n1; v1 = v0 * n1 + v1 * c1; v0 = t;
                t = v2 * c2 - v3 * n2; v3 = v2 * n2 + v3 * c2; v2 = t;
            }
            split_store(Xh, Xl, (size_t)r * DIM_ + c, v0, v1);
            split_store(Xh, Xl, (size_t)(r + 8) * DIM_ + c, v2, v3);
        }
    }
}

// ============================================================================
// split5: one launch splits x, wq, wk, wv, wo  (blockIdx.y selects tensor)
// ============================================================================
__global__ void split5(const float* __restrict__ x,  const float* __restrict__ wq,
                       const float* __restrict__ wk, const float* __restrict__ wv,
                       const float* __restrict__ wo,
                       __nv_bfloat16* xh,  __nv_bfloat16* xl,
                       __nv_bfloat16* qh,  __nv_bfloat16* ql,
                       __nv_bfloat16* kh,  __nv_bfloat16* kl,
                       __nv_bfloat16* vh,  __nv_bfloat16* vl,
                       __nv_bfloat16* oh,  __nv_bfloat16* ol)
{
    const float* src; __nv_bfloat16 *hi, *lo;
    switch (blockIdx.y) {
        case 0: src = x;  hi = xh; lo = xl; break;
        case 1: src = wq; hi = qh; lo = ql; break;
        case 2: src = wk; hi = kh; lo = kl; break;
        case 3: src = wv; hi = vh; lo = vl; break;
        default: src = wo; hi = oh; lo = ol; break;
    }
    size_t i = (size_t)blockIdx.x * blockDim.x + threadIdx.x;
    float4 v = ((const float4*)src)[i];
    __nv_bfloat16 h0 = __float2bfloat16(v.x);
    __nv_bfloat16 h1 = __float2bfloat16(v.y);
    __nv_bfloat16 h2 = __float2bfloat16(v.z);
    __nv_bfloat16 h3 = __float2bfloat16(v.w);
    ((__nv_bfloat162*)hi)[2 * i]     = __nv_bfloat162(h0, h1);
    ((__nv_bfloat162*)hi)[2 * i + 1] = __nv_bfloat162(h2, h3);
    ((__nv_bfloat162*)lo)[2 * i] = __nv_bfloat162(
        __float2bfloat16(v.x - __bfloat162float(h0)),
        __float2bfloat16(v.y - __bfloat162float(h1)));
    ((__nv_bfloat162*)lo)[2 * i + 1] = __nv_bfloat162(
        __float2bfloat16(v.z - __bfloat162float(h2)),
        __float2bfloat16(v.w - __bfloat162float(h3)));
}

// ============================================================================
// adapter GEMV (fp32)
// ============================================================================
__global__ __launch_bounds__(256)
void adapter_gemv(const float* __restrict__ A, const float* __restrict__ W,
                  float* __restrict__ out)
{
    int warp = (blockIdx.x * blockDim.x + threadIdx.x) >> 5;
    int lane = threadIdx.x & 31;
    int e0 = warp * 4;

    float acc[ADL_][4];
#pragma unroll
    for (int l = 0; l < ADL_; l++)
#pragma unroll
        for (int j = 0; j < 4; j++) acc[l][j] = 0.f;

    for (int d = lane * 4; d < DIM_; d += 128) {
        float4 w4[4];
#pragma unroll
        for (int j = 0; j < 4; j++)
            w4[j] = *(const float4*)(W + (size_t)(e0 + j) * DIM_ + d);
#pragma unroll
        for (int l = 0; l < ADL_; l++) {
            float4 a4 = *(const float4*)(A + (size_t)l * DIM_ + d);
#pragma unroll
            for (int j = 0; j < 4; j++) {
                acc[l][j] = fmaf(a4.x, w4[j].x, acc[l][j]);
                acc[l][j] = fmaf(a4.y, w4[j].y, acc[l][j]);
                acc[l][j] = fmaf(a4.z, w4[j].z, acc[l][j]);
                acc[l][j] = fmaf(a4.w, w4[j].w, acc[l][j]);
            }
        }
    }
#pragma unroll
    for (int l = 0; l < ADL_; l++)
#pragma unroll
        for (int j = 0; j < 4; j++) {
            float v = acc[l][j];
#pragma unroll
            for (int off = 16; off; off >>= 1)
                v += __shfl_xor_sync(0xffffffffu, v, off);
            if (lane == 0) out[l * DIM_ + e0 + j] = v;
        }
}

// ============================================================================
// Flash attention (HMMA bf16x3) + fused adapter attention + bf16-split output
// ============================================================================
#define FRSTR   272
#define FQ_TILE (128 * FRSTR)
#define FK_TILE (64 * FRSTR)
#define FSTAGE  (4 * FK_TILE)
#define FAK_OFF (2 * FQ_TILE + 2 * FSTAGE)            // 208896
#define FLASH_SMEM (FAK_OFF + 2 * ADL_ * D_ * 4)      // +10240 = 219136

__device__ __forceinline__ void fkv_fill(uint32_t sdst,
    const __nv_bfloat16* __restrict__ Kh, const __nv_bfloat16* __restrict__ Kl,
    const __nv_bfloat16* __restrict__ Vh, const __nv_bfloat16* __restrict__ Vl,
    int b, int h, int kv0)
{
    const int tid = threadIdx.x;
    const size_t gbase = ((size_t)(b * S_) + kv0) * DIM_ + h * D_;
#pragma unroll
    for (int i = 0; i < 16; i++) {
        int idx = tid + i * 256;
        int arr = idx >> 10;
        int rem = idx & 1023;
        int row = rem >> 4;
        int ch  = rem & 15;
        const __nv_bfloat16* src =
            (arr == 0) ? Kh : (arr == 1) ? Kl : (arr == 2) ? Vh : Vl;
        CP_ASYNC16(sdst + arr * FK_TILE + row * FRSTR + ch * 16,
                   src + gbase + (size_t)row * DIM_ + ch * 8);
    }
}

__global__ __launch_bounds__(256, 1)
void flash_mma(const __nv_bfloat16* __restrict__ Qh_g, const __nv_bfloat16* __restrict__ Ql_g,
               const __nv_bfloat16* __restrict__ Kh_g, const __nv_bfloat16* __restrict__ Kl_g,
               const __nv_bfloat16* __restrict__ Vh_g, const __nv_bfloat16* __restrict__ Vl_g,
               const float* __restrict__ aK, const float* __restrict__ aV,
               const float* __restrict__ gate,
               __nv_bfloat16* __restrict__ Oh, __nv_bfloat16* __restrict__ Ol)
{
    extern __shared__ char sm[];
    const uint32_t base = smem_u32(sm);
    const int tid  = threadIdx.x;
    const int wid  = tid >> 5;
    const int lane = tid & 31;
    const int qt = blockIdx.x, h = blockIdx.y, b = blockIdx.z;
    const int nkt = 2 * qt + 2;

    const uint32_t sQh = base;
    const uint32_t sKV = base + 2 * FQ_TILE;
    float* aKs = (float*)(sm + FAK_OFF);
    float* aVs = aKs + ADL_ * D_;

    // Q tile fill + adapter K/V stage
    {
        size_t gq = ((size_t)(b * S_) + qt * 128) * DIM_ + h * D_;
#pragma unroll
        for (int i = 0; i < 8; i++) {
            int idx = tid + i * 256;
            int row = idx >> 4, ch = idx & 15;
            uint32_t d = row * FRSTR + ch * 16;
            size_t src = gq + (size_t)row * DIM_ + ch * 8;
            CP_ASYNC16(sQh + d,           Qh_g + src);
            CP_ASYNC16(sQh + FQ_TILE + d, Ql_g + src);
        }
        for (int idx = tid; idx < ADL_ * D_; idx += 256) {
            int t = idx >> 7, cc = idx & (D_ - 1);
            aKs[idx] = aK[t * DIM_ + h * D_ + cc];
            aVs[idx] = aV[t * DIM_ + h * D_ + cc];
        }
    }
    fkv_fill(sKV, Kh_g, Kl_g, Vh_g, Vl_g, b, h, 0);
    CP_COMMIT();

    const int q0  = qt * 128 + wid * 16;
    const int qg0 = q0 + (lane >> 2);
    const int qg1 = qg0 + 8;
    const float scl = 0.08838834764831845f;

    float m0 = -1e30f, m1 = -1e30f, l0 = 0.f, l1 = 0.f;
    float o[16][4];
#pragma unroll
    for (int d = 0; d < 16; d++)
#pragma unroll
        for (int q = 0; q < 4; q++) o[d][q] = 0.f;

    const uint32_t kh16 = (uint32_t)((lane >> 4) * 16);

    for (int kt = 0; kt < nkt; kt++) {
        if (kt + 1 < nkt)
            fkv_fill(sKV + ((kt + 1) & 1) * FSTAGE,
                     Kh_g, Kl_g, Vh_g, Vl_g, b, h, (kt + 1) * 64);
        CP_COMMIT();
        CP_WAIT(1);
        __syncthreads();

        const uint32_t st = sKV + (uint32_t)(kt & 1) * FSTAGE;
        const int kv0 = kt * 64;

        if (kv0 <= q0 + 15) {
            float sa[8][4];
#pragma unroll
            for (int n8 = 0; n8 < 8; n8++)
#pragma unroll
                for (int q = 0; q < 4; q++) sa[n8][q] = 0.f;

            const uint32_t qrow = (uint32_t)(wid * 16 + (lane & 15));
            const uint32_t klrow = (uint32_t)(lane & 15);

#pragma unroll
            for (int ch = 0; ch < 8; ch++) {
                uint32_t qa = sQh + qrow * FRSTR + ch * 32 + kh16;
                uint32_t qh[4], ql[4];
                LDSM_X4(qh[0], qh[1], qh[2], qh[3], qa);
                LDSM_X4(ql[0], ql[1], ql[2], ql[3], qa + FQ_TILE);
#pragma unroll
                for (int nb = 0; nb < 4; nb++) {
                    uint32_t ka = st + (klrow + nb * 16) * FRSTR + ch * 32 + kh16;
                    uint32_t r0, r1, r2, r3, t0, t1, t2, t3;
                    LDSM_X4(r0, r1, r2, r3, ka);
                    LDSM_X4(t0, t1, t2, t3, ka + FK_TILE);
                    uint32_t kb0[2] = {r0, r2}, kb1[2] = {r1, r3};
                    uint32_t lb0[2] = {t0, t2}, lb1[2] = {t1, t3};
                    MMA16816(sa[2 * nb],     qh, kb0);
                    MMA16816(sa[2 * nb],     qh, lb0);
                    MMA16816(sa[2 * nb],     ql, kb0);
                    MMA16816(sa[2 * nb + 1], qh, kb1);
                    MMA16816(sa[2 * nb + 1], qh, lb1);
                    MMA16816(sa[2 * nb + 1], ql, kb1);
                }
            }

            float rmax0 = -1e30f, rmax1 = -1e30f;
            const int kvb = kv0 + (lane & 3) * 2;
#pragma unroll
            for (int n8 = 0; n8 < 8; n8++) {
                int kvc = kvb + n8 * 8;
                float s0 = sa[n8][0] * scl, s1 = sa[n8][1] * scl;
                float s2 = sa[n8][2] * scl, s3 = sa[n8][3] * scl;
                if (kvc     > qg0) s0 = -1e30f;
                if (kvc + 1 > qg0) s1 = -1e30f;
                if (kvc     > qg1) s2 = -1e30f;
                if (kvc + 1 > qg1) s3 = -1e30f;
                sa[n8][0] = s0; sa[n8][1] = s1; sa[n8][2] = s2; sa[n8][3] = s3;
                rmax0 = fmaxf(rmax0, fmaxf(s0, s1));
                rmax1 = fmaxf(rmax1, fmaxf(s2, s3));
            }
            rmax0 = fmaxf(rmax0, __shfl_xor_sync(0xffffffffu, rmax0, 1));
            rmax0 = fmaxf(rmax0, __shfl_xor_sync(0xffffffffu, rmax0, 2));
            rmax1 = fmaxf(rmax1, __shfl_xor_sync(0xffffffffu, rmax1, 1));
            rmax1 = fmaxf(rmax1, __shfl_xor_sync(0xffffffffu, rmax1, 2));

            float mn0 = fmaxf(m0, rmax0), mn1 = fmaxf(m1, rmax1);
            float sc0 = __expf(m0 - mn0), sc1 = __expf(m1 - mn1);
            m0 = mn0; m1 = mn1;

            uint32_t ph[16], pl[16];
            float rs0 = 0.f, rs1 = 0.f;
#pragma unroll
            for (int n8 = 0; n8 < 8; n8++) {
                float p0 = __expf(sa[n8][0] - mn0);
                float p1 = __expf(sa[n8][1] - mn0);
                float p2 = __expf(sa[n8][2] - mn1);
                float p3 = __expf(sa[n8][3] - mn1);
                rs0 += p0 + p1; rs1 += p2 + p3;
                float h0 = __bfloat162float(__float2bfloat16(p0));
                float h1 = __bfloat162float(__float2bfloat16(p1));
                float h2 = __bfloat162float(__float2bfloat16(p2));
                float h3 = __bfloat162float(__float2bfloat16(p3));
                ph[2 * n8]     = pack_bf16x2(h0, h1);
                ph[2 * n8 + 1] = pack_bf16x2(h2, h3);
                pl[2 * n8]     = pack_bf16x2(p0 - h0, p1 - h1);
                pl[2 * n8 + 1] = pack_bf16x2(p2 - h2, p3 - h3);
            }
            rs0 += __shfl_xor_sync(0xffffffffu, rs0, 1);
            rs0 += __shfl_xor_sync(0xffffffffu, rs0, 2);
            rs1 += __shfl_xor_sync(0xffffffffu, rs1, 1);
            rs1 += __shfl_xor_sync(0xffffffffu, rs1, 2);
            l0 = l0 * sc0 + rs0;
            l1 = l1 * sc1 + rs1;

#pragma unroll
            for (int d = 0; d < 16; d++) {
                o[d][0] *= sc0; o[d][1] *= sc0;
                o[d][2] *= sc1; o[d][3] *= sc1;
            }

#pragma unroll
            for (int j = 0; j < 4; j++) {
                uint32_t ah[4] = {ph[4*j], ph[4*j+1], ph[4*j+2], ph[4*j+3]};
                uint32_t al[4] = {pl[4*j], pl[4*j+1], pl[4*j+2], pl[4*j+3]};
#pragma unroll
                for (int nb = 0; nb < 8; nb++) {
                    uint32_t va = st + 2 * FK_TILE +
                                  (uint32_t)(j * 16 + (lane & 15)) * FRSTR +
                                  nb * 32 + kh16;
                    uint32_t r0, r1, r2, r3, t0, t1, t2, t3;
                    LDSM_X4_T(r0, r1, r2, r3, va);
                    LDSM_X4_T(t0, t1, t2, t3, va + FK_TILE);
                    uint32_t vh0[2] = {r0, r1}, vh1[2] = {r2, r3};
                    uint32_t vl0[2] = {t0, t1}, vl1[2] = {t2, t3};
                    MMA16816(o[2 * nb],     ah, vh0);
                    MMA16816(o[2 * nb],     ah, vl0);
                    MMA16816(o[2 * nb],     al, vh0);
                    MMA16816(o[2 * nb + 1], ah, vh1);
                    MMA16816(o[2 * nb + 1], ah, vl1);
                    MMA16816(o[2 * nb + 1], al, vh1);
                }
            }
        }
        __syncthreads();
    }

    // ---- epilogue: fused adapter attention + bf16 split store ----
    const float g = tanhf(gate[h]);
    const float inv0 = 1.0f / l0, inv1 = 1.0f / l1;
    const int ccb = (lane & 3) * 2;

#pragma unroll
    for (int rr = 0; rr < 2; rr++) {
        const int lr = wid * 16 + (lane >> 2) + rr * 8;
        const float inv = rr ? inv1 : inv0;
        const size_t rowg = (size_t)(b * S_) + qt * 128 + lr;

        // reconstruct this thread's 32 q columns from smem
        float qv[32];
#pragma unroll
        for (int d = 0; d < 16; d++) {
            int cc = d * 8 + ccb;
            __nv_bfloat162 hh = *(__nv_bfloat162*)(sm + lr * FRSTR + cc * 2);
            __nv_bfloat162 ll = *(__nv_bfloat162*)(sm + FQ_TILE + lr * FRSTR + cc * 2);
            qv[2 * d]     = __bfloat162float(hh.x) + __bfloat162float(ll.x);
            qv[2 * d + 1] = __bfloat162float(hh.y) + __bfloat162float(ll.y);
        }
        // scores over 10 adapter tokens (quad-distributed dot products)
        float sc[ADL_];
#pragma unroll
        for (int t = 0; t < ADL_; t++) {
            float p = 0.f;
#pragma unroll
            for (int d = 0; d < 16; d++) {
                int cc = d * 8 + ccb;
                p = fmaf(qv[2 * d],     aKs[t * D_ + cc],     p);
                p = fmaf(qv[2 * d + 1], aKs[t * D_ + cc + 1], p);
            }
            p += __shfl_xor_sync(0xffffffffu, p, 1);
            p += __shfl_xor_sync(0xffffffffu, p, 2);
            sc[t] = p * scl;
        }
        float mx = sc[0];
#pragma unroll
        for (int t = 1; t < ADL_; t++) mx = fmaxf(mx, sc[t]);
        float sum = 0.f;
#pragma unroll
        for (int t = 0; t < ADL_; t++) { sc[t] = __expf(sc[t] - mx); sum += sc[t]; }
        float isum = g / sum;
#pragma unroll
        for (int t = 0; t < ADL_; t++) sc[t] *= isum;

#pragma unroll
        for (int d = 0; d < 16; d++) {
            int cc = d * 8 + ccb;
            float a0 = 0.f, a1 = 0.f;
#pragma unroll
            for (int t = 0; t < ADL_; t++) {
                a0 = fmaf(sc[t], aVs[t * D_ + cc],     a0);
                a1 = fmaf(sc[t], aVs[t * D_ + cc + 1], a1);
            }
            float o0 = o[d][rr * 2]     * inv + a0;
            float o1 = o[d][rr * 2 + 1] * inv + a1;
            split_store(Oh, Ol, rowg * DIM_ + h * D_ + cc, o0, o1);
        }
    }
}

// ============================================================================
// launch
// ============================================================================
extern "C" void kernel_launch(void* const* d_in, const int* in_sizes, int n_in,
                              void* d_out, int out_size)
{
    const float* x       = (const float*)d_in[0];
    const float* wq      = (const float*)d_in[1];
    const float* wk      = (const float*)d_in[2];
    const float* wv      = (const float*)d_in[3];
    const float* wo      = (const float*)d_in[4];
    const float* gate    = (const float*)d_in[5];
    const float* adapter = (const float*)d_in[6];
    const float* fcos    = (const float*)d_in[7];
    const float* fsin    = (const float*)d_in[8];
    float* out = (float*)d_out;

    float *aKp, *aVp;
    cudaGetSymbolAddress((void**)&aKp, g_aK);
    cudaGetSymbolAddress((void**)&aVp, g_aV);

    __nv_bfloat16 *xh, *xl, *wqh, *wql, *wkh, *wkl, *wvh, *wvl, *woh, *wol;
    __nv_bfloat16 *qh, *ql, *kh, *kl, *vh, *vl, *oh, *ol;
    cudaGetSymbolAddress((void**)&xh,  g_xh);  cudaGetSymbolAddress((void**)&xl,  g_xl);
    cudaGetSymbolAddress((void**)&wqh, g_wqh); cudaGetSymbolAddress((void**)&wql, g_wql);
    cudaGetSymbolAddress((void**)&wkh, g_wkh); cudaGetSymbolAddress((void**)&wkl, g_wkl);
    cudaGetSymbolAddress((void**)&wvh, g_wvh); cudaGetSymbolAddress((void**)&wvl, g_wvl);
    cudaGetSymbolAddress((void**)&woh, g_woh); cudaGetSymbolAddress((void**)&wol, g_wol);
    cudaGetSymbolAddress((void**)&qh,  g_qh);  cudaGetSymbolAddress((void**)&ql,  g_ql);
    cudaGetSymbolAddress((void**)&kh,  g_kh);  cudaGetSymbolAddress((void**)&kl,  g_kl);
    cudaGetSymbolAddress((void**)&vh,  g_vh);  cudaGetSymbolAddress((void**)&vl,  g_vl);
    cudaGetSymbolAddress((void**)&oh,  g_oh);  cudaGetSymbolAddress((void**)&ol,  g_ol);

    cudaFuncSetAttribute(mma_gemm,
                         cudaFuncAttributeMaxDynamicSharedMemorySize, GK_SMEM);
    cudaFuncSetAttribute(qkv_gemm,
                         cudaFuncAttributeMaxDynamicSharedMemorySize, GK_SMEM);
    cudaFuncSetAttribute(flash_mma,
                         cudaFuncAttributeMaxDynamicSharedMemorySize, FLASH_SMEM);

    // 1: all input splits in one launch
    split5<<<dim3(NELEM / 4 / 256, 5), 256>>>(x, wq, wk, wv, wo,
        xh, xl, wqh, wql, wkh, wkl, wvh, wvl, woh, wol);

    // 2-3: adapter projections (fp32, independent of splits)
    adapter_gemv<<<128, 256>>>(adapter, wk, aKp);
    adapter_gemv<<<128, 256>>>(adapter, wv, aVp);

    // 4: fused QKV GEMM (+rope, +bf16 split)
    qkv_gemm<<<dim3(DIM_ / 128, MROWS / 128, 3), 256, GK_SMEM>>>(
        xh, xl, wqh, wql, wkh, wkl, wvh, wvl,
        qh, ql, kh, kl, vh, vl, fcos, fsin);

    // 5: flash attention (+adapter attention, +bf16 split out)
    flash_mma<<<dim3(S_ / 128, H_, B_), 256, FLASH_SMEM>>>(
        qh, ql, kh, kl, vh, vl, aKp, aVp, gate, oh, ol);

    // 6: output projection (fp32 out)
    mma_gemm<<<dim3(DIM_ / 128, MROWS / 128), 256, GK_SMEM>>>(
        oh, ol, woh, wol, out);
}

// round 7
// speedup vs baseline: 1.1206x; 1.1206x over previous
#include <cuda_runtime.h>
#include <cuda_bf16.h>
#include <math.h>
#include <stdint.h>

// ---------------------------------------------------------------- constants
#define B_    2
#define S_    2048
#define H_    32
#define D_    128
#define DIM_  4096
#define ADL_  10
#define MROWS (B_ * S_)
#define NELEM ((size_t)MROWS * DIM_)

// ---------------------------------------------------------------- scratch
__device__ float g_aK[ADL_ * DIM_];
__device__ float g_aV[ADL_ * DIM_];

__device__ __nv_bfloat16 g_xh[NELEM],  g_xl[NELEM];
__device__ __nv_bfloat16 g_wqh[NELEM], g_wql[NELEM];
__device__ __nv_bfloat16 g_wkh[NELEM], g_wkl[NELEM];
__device__ __nv_bfloat16 g_wvh[NELEM], g_wvl[NELEM];
__device__ __nv_bfloat16 g_woh[NELEM], g_wol[NELEM];
__device__ __nv_bfloat16 g_qh[NELEM],  g_ql[NELEM];
__device__ __nv_bfloat16 g_kh[NELEM],  g_kl[NELEM];
__device__ __nv_bfloat16 g_vh[NELEM],  g_vl[NELEM];
__device__ __nv_bfloat16 g_oh[NELEM],  g_ol[NELEM];

// ---------------------------------------------------------------- PTX utils
__device__ __forceinline__ uint32_t smem_u32(const void* p) {
    uint32_t a;
    asm("{ .reg .u64 t; cvta.to.shared.u64 t, %1; cvt.u32.u64 %0, t; }"
        : "=r"(a) : "l"(p));
    return a;
}
#define CP_ASYNC16(dst, src) \
    asm volatile("cp.async.cg.shared.global [%0], [%1], 16;" \
                 :: "r"(dst), "l"(src) : "memory")
#define CP_COMMIT() asm volatile("cp.async.commit_group;" ::: "memory")
#define CP_WAIT(n)  asm volatile("cp.async.wait_group %0;" :: "n"(n) : "memory")

#define LDSM_X4(r0, r1, r2, r3, addr) \
    asm volatile("ldmatrix.sync.aligned.m8n8.x4.shared.b16 {%0,%1,%2,%3}, [%4];" \
                 : "=r"(r0), "=r"(r1), "=r"(r2), "=r"(r3) : "r"(addr))
#define LDSM_X4_T(r0, r1, r2, r3, addr) \
    asm volatile("ldmatrix.sync.aligned.m8n8.x4.trans.shared.b16 {%0,%1,%2,%3}, [%4];" \
                 : "=r"(r0), "=r"(r1), "=r"(r2), "=r"(r3) : "r"(addr))

#define MMA16816(c, a, b) \
    asm volatile("mma.sync.aligned.m16n8k16.row.col.f32.bf16.bf16.f32 " \
                 "{%0,%1,%2,%3}, {%4,%5,%6,%7}, {%8,%9}, {%0,%1,%2,%3};" \
                 : "+f"((c)[0]), "+f"((c)[1]), "+f"((c)[2]), "+f"((c)[3]) \
                 : "r"((a)[0]), "r"((a)[1]), "r"((a)[2]), "r"((a)[3]), \
                   "r"((b)[0]), "r"((b)[1]))

__device__ __forceinline__ uint32_t pack_bf16x2(float lo, float hi) {
    __nv_bfloat162 t = __floats2bfloat162_rn(lo, hi);
    return *(uint32_t*)&t;
}
__device__ __forceinline__ void split_store(__nv_bfloat16* Xh, __nv_bfloat16* Xl,
                                            size_t off, float v0, float v1) {
    __nv_bfloat16 h0 = __float2bfloat16(v0);
    __nv_bfloat16 h1 = __float2bfloat16(v1);
    __nv_bfloat16 l0 = __float2bfloat16(v0 - __bfloat162float(h0));
    __nv_bfloat16 l1 = __float2bfloat16(v1 - __bfloat162float(h1));
    *(__nv_bfloat162*)(Xh + off) = __nv_bfloat162(h0, h1);
    *(__nv_bfloat162*)(Xl + off) = __nv_bfloat162(l0, l1);
}

// ============================================================================
// GEMM core (bf16x3 HMMA, 128x128 CTA tile, BK=32, 2-stage, 2 CTAs/SM)
// ============================================================================
#define GK_BK      32
#define GK_TILE_B  10240
#define GK_STAGE_B (4 * GK_TILE_B)
#define GK_STAGES  2
#define GK_SMEM    (GK_STAGES * GK_STAGE_B)    // 81920 -> 2 CTAs/SM
#define GK_NIT     (DIM_ / GK_BK)

__device__ __forceinline__ void gk_fill(uint32_t sbase,
    const __nv_bfloat16* __restrict__ Ah, const __nv_bfloat16* __restrict__ Al,
    const __nv_bfloat16* __restrict__ Bh, const __nv_bfloat16* __restrict__ Bl,
    int rowBase, int colBase, int k0)
{
    const int tid = threadIdx.x;
#pragma unroll
    for (int i = 0; i < 2; i++) {
        int idx = tid + i * 256;
        int row = idx >> 2;
        int cg  = (idx & 3) * 8;
        uint32_t doff = (uint32_t)(row * 80 + (idx & 3) * 16);
        size_t ga = (size_t)(rowBase + row) * DIM_ + k0 + cg;
        size_t gb = (size_t)(colBase + row) * DIM_ + k0 + cg;
        CP_ASYNC16(sbase + doff,                 Ah + ga);
        CP_ASYNC16(sbase + GK_TILE_B + doff,     Al + ga);
        CP_ASYNC16(sbase + 2 * GK_TILE_B + doff, Bh + gb);
        CP_ASYNC16(sbase + 3 * GK_TILE_B + doff, Bl + gb);
    }
}

// 2-stage mainloop: wait stage it, then issue fill of stage it+1 (its buffer
// was freed by the barrier), then compute stage it. Cross-CTA overlap hides
// the exposed fill latency.
#define GK_MAINLOOP(Ah, Al, Bh, Bl)                                            \
    gk_fill(base, Ah, Al, Bh, Bl, rowBase, colBase, 0);                        \
    CP_COMMIT();                                                               \
    const uint32_t aRow = (uint32_t)(wm + (lane & 15));                        \
    const uint32_t bRow = (uint32_t)(wn + (lane & 15));                        \
    const uint32_t kHalf = (uint32_t)((lane >> 4) * 16);                       \
    for (int it = 0; it < GK_NIT; it++) {                                      \
        CP_WAIT(0);                                                            \
        __syncthreads();                                                       \
        if (it + 1 < GK_NIT)                                                   \
            gk_fill(base + (uint32_t)((it + 1) & 1) * GK_STAGE_B,              \
                    Ah, Al, Bh, Bl, rowBase, colBase, (it + 1) * GK_BK);       \
        CP_COMMIT();                                                           \
        const uint32_t sb = base + (uint32_t)(it & 1) * GK_STAGE_B;            \
        _Pragma("unroll")                                                      \
        for (int ks = 0; ks < 2; ks++) {                                       \
            const uint32_t kcol = (uint32_t)(ks * 32) + kHalf;                 \
            uint32_t ah[4][4], al[4][4], bh[4][2], bl[4][2];                   \
            _Pragma("unroll")                                                  \
            for (int mi = 0; mi < 4; mi++) {                                   \
                uint32_t off = (aRow + mi * 16) * 80 + kcol;                   \
                LDSM_X4(ah[mi][0], ah[mi][1], ah[mi][2], ah[mi][3], sb + off); \
                LDSM_X4(al[mi][0], al[mi][1], al[mi][2], al[mi][3],            \
                        sb + GK_TILE_B + off);                                 \
            }                                                                  \
            _Pragma("unroll")                                                  \
            for (int np = 0; np < 2; np++) {                                   \
                uint32_t off = (bRow + np * 16) * 80 + kcol;                   \
                uint32_t r0, r1, r2, r3;                                       \
                LDSM_X4(r0, r1, r2, r3, sb + 2 * GK_TILE_B + off);             \
                bh[2 * np][0] = r0; bh[2 * np][1] = r2;                        \
                bh[2 * np + 1][0] = r1; bh[2 * np + 1][1] = r3;                \
                LDSM_X4(r0, r1, r2, r3, sb + 3 * GK_TILE_B + off);             \
                bl[2 * np][0] = r0; bl[2 * np][1] = r2;                        \
                bl[2 * np + 1][0] = r1; bl[2 * np + 1][1] = r3;                \
            }                                                                  \
            _Pragma("unroll")                                                  \
            for (int mi = 0; mi < 4; mi++)                                     \
                _Pragma("unroll")                                              \
                for (int ni = 0; ni < 4; ni++) {                               \
                    MMA16816(acc[mi][ni], ah[mi], bh[ni]);                     \
                    MMA16816(acc[mi][ni], ah[mi], bl[ni]);                     \
                    MMA16816(acc[mi][ni], al[mi], bh[ni]);                     \
                }                                                              \
        }                                                                      \
    }

// --------- final output GEMM: fp32 C ---------
__global__ __launch_bounds__(256, 2)
void mma_gemm(const __nv_bfloat16* __restrict__ Ah, const __nv_bfloat16* __restrict__ Al,
              const __nv_bfloat16* __restrict__ Bh, const __nv_bfloat16* __restrict__ Bl,
              float* __restrict__ C)
{
    extern __shared__ char sm[];
    const uint32_t base = smem_u32(sm);
    const int lane = threadIdx.x & 31;
    const int wid  = threadIdx.x >> 5;
    const int rowBase = blockIdx.y * 128;
    const int colBase = blockIdx.x * 128;
    const int wm = (wid & 1) * 64;
    const int wn = (wid >> 1) * 32;

    float acc[4][4][4];
#pragma unroll
    for (int mi = 0; mi < 4; mi++)
#pragma unroll
        for (int ni = 0; ni < 4; ni++)
#pragma unroll
            for (int q = 0; q < 4; q++) acc[mi][ni][q] = 0.f;

    GK_MAINLOOP(Ah, Al, Bh, Bl)

    const int r0 = rowBase + wm + (lane >> 2);
    const int c0 = colBase + wn + (lane & 3) * 2;
#pragma unroll
    for (int mi = 0; mi < 4; mi++)
#pragma unroll
        for (int ni = 0; ni < 4; ni++) {
            float* p = C + (size_t)(r0 + mi * 16) * DIM_ + c0 + ni * 8;
            *(float2*)p = make_float2(acc[mi][ni][0], acc[mi][ni][1]);
            *(float2*)(p + 8 * DIM_) = make_float2(acc[mi][ni][2], acc[mi][ni][3]);
        }
}

// --------- QKV GEMM: z selects weights/output; rope fused for z<2 ---------
__global__ __launch_bounds__(256, 2)
void qkv_gemm(const __nv_bfloat16* __restrict__ Ah, const __nv_bfloat16* __restrict__ Al,
              const __nv_bfloat16* __restrict__ Bqh, const __nv_bfloat16* __restrict__ Bql,
              const __nv_bfloat16* __restrict__ Bkh, const __nv_bfloat16* __restrict__ Bkl,
              const __nv_bfloat16* __restrict__ Bvh, const __nv_bfloat16* __restrict__ Bvl,
              __nv_bfloat16* __restrict__ Qh, __nv_bfloat16* __restrict__ Ql,
              __nv_bfloat16* __restrict__ Kh, __nv_bfloat16* __restrict__ Kl,
              __nv_bfloat16* __restrict__ Vh, __nv_bfloat16* __restrict__ Vl,
              const float* __restrict__ fcos, const float* __restrict__ fsin)
{
    extern __shared__ char sm[];
    const uint32_t base = smem_u32(sm);
    const int lane = threadIdx.x & 31;
    const int wid  = threadIdx.x >> 5;
    const int rowBase = blockIdx.y * 128;
    const int colBase = blockIdx.x * 128;
    const int wm = (wid & 1) * 64;
    const int wn = (wid >> 1) * 32;
    const int z = blockIdx.z;

    const __nv_bfloat16* Bh = (z == 0) ? Bqh : (z == 1) ? Bkh : Bvh;
    const __nv_bfloat16* Bl = (z == 0) ? Bql : (z == 1) ? Bkl : Bvl;
    __nv_bfloat16* Xh = (z == 0) ? Qh : (z == 1) ? Kh : Vh;
    __nv_bfloat16* Xl = (z == 0) ? Ql : (z == 1) ? Kl : Vl;
    const bool dorope = (z < 2);

    float acc[4][4][4];
#pragma unroll
    for (int mi = 0; mi < 4; mi++)
#pragma unroll
        for (int ni = 0; ni < 4; ni++)
#pragma unroll
            for (int q = 0; q < 4; q++) acc[mi][ni][q] = 0.f;

    GK_MAINLOOP(Ah, Al, Bh, Bl)

    const int r0 = rowBase + wm + (lane >> 2);
    const int c0 = colBase + wn + (lane & 3) * 2;
#pragma unroll
    for (int mi = 0; mi < 4; mi++) {
        int r  = r0 + mi * 16;
        int s1 = r & (S_ - 1);
        int s2 = (r + 8) & (S_ - 1);
#pragma unroll
        for (int ni = 0; ni < 4; ni++) {
            int c = c0 + ni * 8;
            float v0 = acc[mi][ni][0], v1 = acc[mi][ni][1];
            float v2 = acc[mi][ni][2], v3 = acc[mi][ni][3];
            if (dorope) {
                int i = (c & (D_ - 1)) >> 1;
                float c1 = fcos[s1 * 64 + i], n1 = fsin[s1 * 64 + i];
                float c2 = fcos[s2 * 64 + i], n2 = fsin[s2 * 64 + i];
                float t;
                t = v0 * c1 - v1 * n1; v1 = v0 * n1 + v1 * c1; v0 = t;
                t = v2 * c2 - v3 * n2; v3 = v2 * n2 + v3 * c2; v2 = t;
            }
            split_store(Xh, Xl, (size_t)r * DIM_ + c, v0, v1);
            split_store(Xh, Xl, (size_t)(r + 8) * DIM_ + c, v2, v3);
        }
    }
}

// ============================================================================
// split5: one launch splits x, wq, wk, wv, wo
// ============================================================================
__global__ void split5(const float* __restrict__ x,  const float* __restrict__ wq,
                       const float* __restrict__ wk, const float* __restrict__ wv,
                       const float* __restrict__ wo,
                       __nv_bfloat16* xh,  __nv_bfloat16* xl,
                       __nv_bfloat16* qh,  __nv_bfloat16* ql,
                       __nv_bfloat16* kh,  __nv_bfloat16* kl,
                       __nv_bfloat16* vh,  __nv_bfloat16* vl,
                       __nv_bfloat16* oh,  __nv_bfloat16* ol)
{
    const float* src; __nv_bfloat16 *hi, *lo;
    switch (blockIdx.y) {
        case 0: src = x;  hi = xh; lo = xl; break;
        case 1: src = wq; hi = qh; lo = ql; break;
        case 2: src = wk; hi = kh; lo = kl; break;
        case 3: src = wv; hi = vh; lo = vl; break;
        default: src = wo; hi = oh; lo = ol; break;
    }
    size_t i = (size_t)blockIdx.x * blockDim.x + threadIdx.x;
    float4 v = ((const float4*)src)[i];
    __nv_bfloat16 h0 = __float2bfloat16(v.x);
    __nv_bfloat16 h1 = __float2bfloat16(v.y);
    __nv_bfloat16 h2 = __float2bfloat16(v.z);
    __nv_bfloat16 h3 = __float2bfloat16(v.w);
    ((__nv_bfloat162*)hi)[2 * i]     = __nv_bfloat162(h0, h1);
    ((__nv_bfloat162*)hi)[2 * i + 1] = __nv_bfloat162(h2, h3);
    ((__nv_bfloat162*)lo)[2 * i] = __nv_bfloat162(
        __float2bfloat16(v.x - __bfloat162float(h0)),
        __float2bfloat16(v.y - __bfloat162float(h1)));
    ((__nv_bfloat162*)lo)[2 * i + 1] = __nv_bfloat162(
        __float2bfloat16(v.z - __bfloat162float(h2)),
        __float2bfloat16(v.w - __bfloat162float(h3)));
}

// ============================================================================
// adapter GEMV (fp32)
// ============================================================================
__global__ __launch_bounds__(256)
void adapter_gemv(const float* __restrict__ A, const float* __restrict__ W,
                  float* __restrict__ out)
{
    int warp = (blockIdx.x * blockDim.x + threadIdx.x) >> 5;
    int lane = threadIdx.x & 31;
    int e0 = warp * 4;

    float acc[ADL_][4];
#pragma unroll
    for (int l = 0; l < ADL_; l++)
#pragma unroll
        for (int j = 0; j < 4; j++) acc[l][j] = 0.f;

    for (int d = lane * 4; d < DIM_; d += 128) {
        float4 w4[4];
#pragma unroll
        for (int j = 0; j < 4; j++)
            w4[j] = *(const float4*)(W + (size_t)(e0 + j) * DIM_ + d);
#pragma unroll
        for (int l = 0; l < ADL_; l++) {
            float4 a4 = *(const float4*)(A + (size_t)l * DIM_ + d);
#pragma unroll
            for (int j = 0; j < 4; j++) {
                acc[l][j] = fmaf(a4.x, w4[j].x, acc[l][j]);
                acc[l][j] = fmaf(a4.y, w4[j].y, acc[l][j]);
                acc[l][j] = fmaf(a4.z, w4[j].z, acc[l][j]);
                acc[l][j] = fmaf(a4.w, w4[j].w, acc[l][j]);
            }
        }
    }
#pragma unroll
    for (int l = 0; l < ADL_; l++)
#pragma unroll
        for (int j = 0; j < 4; j++) {
            float v = acc[l][j];
#pragma unroll
            for (int off = 16; off; off >>= 1)
                v += __shfl_xor_sync(0xffffffffu, v, off);
            if (lane == 0) out[l * DIM_ + e0 + j] = v;
        }
}

// ============================================================================
// Flash attention (HMMA bf16x3) + fused adapter attention + bf16-split output
// ============================================================================
#define FRSTR   272
#define FQ_TILE (128 * FRSTR)
#define FK_TILE (64 * FRSTR)
#define FSTAGE  (4 * FK_TILE)
#define FAK_OFF (2 * FQ_TILE + 2 * FSTAGE)
#define FLASH_SMEM (FAK_OFF + 2 * ADL_ * D_ * 4)

__device__ __forceinline__ void fkv_fill(uint32_t sdst,
    const __nv_bfloat16* __restrict__ Kh, const __nv_bfloat16* __restrict__ Kl,
    const __nv_bfloat16* __restrict__ Vh, const __nv_bfloat16* __restrict__ Vl,
    int b, int h, int kv0)
{
    const int tid = threadIdx.x;
    const size_t gbase = ((size_t)(b * S_) + kv0) * DIM_ + h * D_;
#pragma unroll
    for (int i = 0; i < 16; i++) {
        int idx = tid + i * 256;
        int arr = idx >> 10;
        int rem = idx & 1023;
        int row = rem >> 4;
        int ch  = rem & 15;
        const __nv_bfloat16* src =
            (arr == 0) ? Kh : (arr == 1) ? Kl : (arr == 2) ? Vh : Vl;
        CP_ASYNC16(sdst + arr * FK_TILE + row * FRSTR + ch * 16,
                   src + gbase + (size_t)row * DIM_ + ch * 8);
    }
}

__global__ __launch_bounds__(256, 1)
void flash_mma(const __nv_bfloat16* __restrict__ Qh_g, const __nv_bfloat16* __restrict__ Ql_g,
               const __nv_bfloat16* __restrict__ Kh_g, const __nv_bfloat16* __restrict__ Kl_g,
               const __nv_bfloat16* __restrict__ Vh_g, const __nv_bfloat16* __restrict__ Vl_g,
               const float* __restrict__ aK, const float* __restrict__ aV,
               const float* __restrict__ gate,
               __nv_bfloat16* __restrict__ Oh, __nv_bfloat16* __restrict__ Ol)
{
    extern __shared__ char sm[];
    const uint32_t base = smem_u32(sm);
    const int tid  = threadIdx.x;
    const int wid  = tid >> 5;
    const int lane = tid & 31;
    const int qt = blockIdx.x, h = blockIdx.y, b = blockIdx.z;
    const int nkt = 2 * qt + 2;

    const uint32_t sQh = base;
    const uint32_t sKV = base + 2 * FQ_TILE;
    float* aKs = (float*)(sm + FAK_OFF);
    float* aVs = aKs + ADL_ * D_;

    {
        size_t gq = ((size_t)(b * S_) + qt * 128) * DIM_ + h * D_;
#pragma unroll
        for (int i = 0; i < 8; i++) {
            int idx = tid + i * 256;
            int row = idx >> 4, ch = idx & 15;
            uint32_t d = row * FRSTR + ch * 16;
            size_t src = gq + (size_t)row * DIM_ + ch * 8;
            CP_ASYNC16(sQh + d,           Qh_g + src);
            CP_ASYNC16(sQh + FQ_TILE + d, Ql_g + src);
        }
        for (int idx = tid; idx < ADL_ * D_; idx += 256) {
            int t = idx >> 7, cc = idx & (D_ - 1);
            aKs[idx] = aK[t * DIM_ + h * D_ + cc];
            aVs[idx] = aV[t * DIM_ + h * D_ + cc];
        }
    }
    fkv_fill(sKV, Kh_g, Kl_g, Vh_g, Vl_g, b, h, 0);
    CP_COMMIT();

    const int q0  = qt * 128 + wid * 16;
    const int qg0 = q0 + (lane >> 2);
    const int qg1 = qg0 + 8;
    const float scl = 0.08838834764831845f;

    float m0 = -1e30f, m1 = -1e30f, l0 = 0.f, l1 = 0.f;
    float o[16][4];
#pragma unroll
    for (int d = 0; d < 16; d++)
#pragma unroll
        for (int q = 0; q < 4; q++) o[d][q] = 0.f;

    const uint32_t kh16 = (uint32_t)((lane >> 4) * 16);

    for (int kt = 0; kt < nkt; kt++) {
        if (kt + 1 < nkt)
            fkv_fill(sKV + ((kt + 1) & 1) * FSTAGE,
                     Kh_g, Kl_g, Vh_g, Vl_g, b, h, (kt + 1) * 64);
        CP_COMMIT();
        CP_WAIT(1);
        __syncthreads();

        const uint32_t st = sKV + (uint32_t)(kt & 1) * FSTAGE;
        const int kv0 = kt * 64;

        if (kv0 <= q0 + 15) {
            float sa[8][4];
#pragma unroll
            for (int n8 = 0; n8 < 8; n8++)
#pragma unroll
                for (int q = 0; q < 4; q++) sa[n8][q] = 0.f;

            const uint32_t qrow = (uint32_t)(wid * 16 + (lane & 15));
            const uint32_t klrow = (uint32_t)(lane & 15);

#pragma unroll
            for (int ch = 0; ch < 8; ch++) {
                uint32_t qa = sQh + qrow * FRSTR + ch * 32 + kh16;
                uint32_t qh[4], ql[4];
                LDSM_X4(qh[0], qh[1], qh[2], qh[3], qa);
                LDSM_X4(ql[0], ql[1], ql[2], ql[3], qa + FQ_TILE);
#pragma unroll
                for (int nb = 0; nb < 4; nb++) {
                    uint32_t ka = st + (klrow + nb * 16) * FRSTR + ch * 32 + kh16;
                    uint32_t r0, r1, r2, r3, t0, t1, t2, t3;
                    LDSM_X4(r0, r1, r2, r3, ka);
                    LDSM_X4(t0, t1, t2, t3, ka + FK_TILE);
                    uint32_t kb0[2] = {r0, r2}, kb1[2] = {r1, r3};
                    uint32_t lb0[2] = {t0, t2}, lb1[2] = {t1, t3};
                    MMA16816(sa[2 * nb],     qh, kb0);
                    MMA16816(sa[2 * nb],     qh, lb0);
                    MMA16816(sa[2 * nb],     ql, kb0);
                    MMA16816(sa[2 * nb + 1], qh, kb1);
                    MMA16816(sa[2 * nb + 1], qh, lb1);
                    MMA16816(sa[2 * nb + 1], ql, kb1);
                }
            }

            float rmax0 = -1e30f, rmax1 = -1e30f;
            const int kvb = kv0 + (lane & 3) * 2;
#pragma unroll
            for (int n8 = 0; n8 < 8; n8++) {
                int kvc = kvb + n8 * 8;
                float s0 = sa[n8][0] * scl, s1 = sa[n8][1] * scl;
                float s2 = sa[n8][2] * scl, s3 = sa[n8][3] * scl;
                if (kvc     > qg0) s0 = -1e30f;
                if (kvc + 1 > qg0) s1 = -1e30f;
                if (kvc     > qg1) s2 = -1e30f;
                if (kvc + 1 > qg1) s3 = -1e30f;
                sa[n8][0] = s0; sa[n8][1] = s1; sa[n8][2] = s2; sa[n8][3] = s3;
                rmax0 = fmaxf(rmax0, fmaxf(s0, s1));
                rmax1 = fmaxf(rmax1, fmaxf(s2, s3));
            }
            rmax0 = fmaxf(rmax0, __shfl_xor_sync(0xffffffffu, rmax0, 1));
            rmax0 = fmaxf(rmax0, __shfl_xor_sync(0xffffffffu, rmax0, 2));
            rmax1 = fmaxf(rmax1, __shfl_xor_sync(0xffffffffu, rmax1, 1));
            rmax1 = fmaxf(rmax1, __shfl_xor_sync(0xffffffffu, rmax1, 2));

            float mn0 = fmaxf(m0, rmax0), mn1 = fmaxf(m1, rmax1);
            float sc0 = __expf(m0 - mn0), sc1 = __expf(m1 - mn1);
            m0 = mn0; m1 = mn1;

            uint32_t ph[16], pl[16];
            float rs0 = 0.f, rs1 = 0.f;
#pragma unroll
            for (int n8 = 0; n8 < 8; n8++) {
                float p0 = __expf(sa[n8][0] - mn0);
                float p1 = __expf(sa[n8][1] - mn0);
                float p2 = __expf(sa[n8][2] - mn1);
                float p3 = __expf(sa[n8][3] - mn1);
                rs0 += p0 + p1; rs1 += p2 + p3;
                float h0 = __bfloat162float(__float2bfloat16(p0));
                float h1 = __bfloat162float(__float2bfloat16(p1));
                float h2 = __bfloat162float(__float2bfloat16(p2));
                float h3 = __bfloat162float(__float2bfloat16(p3));
                ph[2 * n8]     = pack_bf16x2(h0, h1);
                ph[2 * n8 + 1] = pack_bf16x2(h2, h3);
                pl[2 * n8]     = pack_bf16x2(p0 - h0, p1 - h1);
                pl[2 * n8 + 1] = pack_bf16x2(p2 - h2, p3 - h3);
            }
            rs0 += __shfl_xor_sync(0xffffffffu, rs0, 1);
            rs0 += __shfl_xor_sync(0xffffffffu, rs0, 2);
            rs1 += __shfl_xor_sync(0xffffffffu, rs1, 1);
            rs1 += __shfl_xor_sync(0xffffffffu, rs1, 2);
            l0 = l0 * sc0 + rs0;
            l1 = l1 * sc1 + rs1;

#pragma unroll
            for (int d = 0; d < 16; d++) {
                o[d][0] *= sc0; o[d][1] *= sc0;
                o[d][2] *= sc1; o[d][3] *= sc1;
            }

#pragma unroll
            for (int j = 0; j < 4; j++) {
                uint32_t ah[4] = {ph[4*j], ph[4*j+1], ph[4*j+2], ph[4*j+3]};
                uint32_t al[4] = {pl[4*j], pl[4*j+1], pl[4*j+2], pl[4*j+3]};
#pragma unroll
                for (int nb = 0; nb < 8; nb++) {
                    uint32_t va = st + 2 * FK_TILE +
                                  (uint32_t)(j * 16 + (lane & 15)) * FRSTR +
                                  nb * 32 + kh16;
                    uint32_t r0, r1, r2, r3, t0, t1, t2, t3;
                    LDSM_X4_T(r0, r1, r2, r3, va);
                    LDSM_X4_T(t0, t1, t2, t3, va + FK_TILE);
                    uint32_t vh0[2] = {r0, r1}, vh1[2] = {r2, r3};
                    uint32_t vl0[2] = {t0, t1}, vl1[2] = {t2, t3};
                    MMA16816(o[2 * nb],     ah, vh0);
                    MMA16816(o[2 * nb],     ah, vl0);
                    MMA16816(o[2 * nb],     al, vh0);
                    MMA16816(o[2 * nb + 1], ah, vh1);
                    MMA16816(o[2 * nb + 1], ah, vl1);
                    MMA16816(o[2 * nb + 1], al, vh1);
                }
            }
        }
        __syncthreads();
    }

    // ---- epilogue: fused adapter attention + bf16 split store ----
    const float g = tanhf(gate[h]);
    const float inv0 = 1.0f / l0, inv1 = 1.0f / l1;
    const int ccb = (lane & 3) * 2;

#pragma unroll
    for (int rr = 0; rr < 2; rr++) {
        const int lr = wid * 16 + (lane >> 2) + rr * 8;
        const float inv = rr ? inv1 : inv0;
        const size_t rowg = (size_t)(b * S_) + qt * 128 + lr;

        float qv[32];
#pragma unroll
        for (int d = 0; d < 16; d++) {
            int cc = d * 8 + ccb;
            __nv_bfloat162 hh = *(__nv_bfloat162*)(sm + lr * FRSTR + cc * 2);
            __nv_bfloat162 ll = *(__nv_bfloat162*)(sm + FQ_TILE + lr * FRSTR + cc * 2);
            qv[2 * d]     = __bfloat162float(hh.x) + __bfloat162float(ll.x);
            qv[2 * d + 1] = __bfloat162float(hh.y) + __bfloat162float(ll.y);
        }
        float sc[ADL_];
#pragma unroll
        for (int t = 0; t < ADL_; t++) {
            float p = 0.f;
#pragma unroll
            for (int d = 0; d < 16; d++) {
                int cc = d * 8 + ccb;
                p = fmaf(qv[2 * d],     aKs[t * D_ + cc],     p);
                p = fmaf(qv[2 * d + 1], aKs[t * D_ + cc + 1], p);
            }
            p += __shfl_xor_sync(0xffffffffu, p, 1);
            p += __shfl_xor_sync(0xffffffffu, p, 2);
            sc[t] = p * scl;
        }
        float mx = sc[0];
#pragma unroll
        for (int t = 1; t < ADL_; t++) mx = fmaxf(mx, sc[t]);
        float sum = 0.f;
#pragma unroll
        for (int t = 0; t < ADL_; t++) { sc[t] = __expf(sc[t] - mx); sum += sc[t]; }
        float isum = g / sum;
#pragma unroll
        for (int t = 0; t < ADL_; t++) sc[t] *= isum;

#pragma unroll
        for (int d = 0; d < 16; d++) {
            int cc = d * 8 + ccb;
            float a0 = 0.f, a1 = 0.f;
#pragma unroll
            for (int t = 0; t < ADL_; t++) {
                a0 = fmaf(sc[t], aVs[t * D_ + cc],     a0);
                a1 = fmaf(sc[t], aVs[t * D_ + cc + 1], a1);
            }
            float o0 = o[d][rr * 2]     * inv + a0;
            float o1 = o[d][rr * 2 + 1] * inv + a1;
            split_store(Oh, Ol, rowg * DIM_ + h * D_ + cc, o0, o1);
        }
    }
}

// ============================================================================
// launch
// ============================================================================
extern "C" void kernel_launch(void* const* d_in, const int* in_sizes, int n_in,
                              void* d_out, int out_size)
{
    const float* x       = (const float*)d_in[0];
    const float* wq      = (const float*)d_in[1];
    const float* wk      = (const float*)d_in[2];
    const float* wv      = (const float*)d_in[3];
    const float* wo      = (const float*)d_in[4];
    const float* gate    = (const float*)d_in[5];
    const float* adapter = (const float*)d_in[6];
    const float* fcos    = (const float*)d_in[7];
    const float* fsin    = (const float*)d_in[8];
    float* out = (float*)d_out;

    float *aKp, *aVp;
    cudaGetSymbolAddress((void**)&aKp, g_aK);
    cudaGetSymbolAddress((void**)&aVp, g_aV);

    __nv_bfloat16 *xh, *xl, *wqh, *wql, *wkh, *wkl, *wvh, *wvl, *woh, *wol;
    __nv_bfloat16 *qh, *ql, *kh, *kl, *vh, *vl, *oh, *ol;
    cudaGetSymbolAddress((void**)&xh,  g_xh);  cudaGetSymbolAddress((void**)&xl,  g_xl);
    cudaGetSymbolAddress((void**)&wqh, g_wqh); cudaGetSymbolAddress((void**)&wql, g_wql);
    cudaGetSymbolAddress((void**)&wkh, g_wkh); cudaGetSymbolAddress((void**)&wkl, g_wkl);
    cudaGetSymbolAddress((void**)&wvh, g_wvh); cudaGetSymbolAddress((void**)&wvl, g_wvl);
    cudaGetSymbolAddress((void**)&woh, g_woh); cudaGetSymbolAddress((void**)&wol, g_wol);
    cudaGetSymbolAddress((void**)&qh,  g_qh);  cudaGetSymbolAddress((void**)&ql,  g_ql);
    cudaGetSymbolAddress((void**)&kh,  g_kh);  cudaGetSymbolAddress((void**)&kl,  g_kl);
    cudaGetSymbolAddress((void**)&vh,  g_vh);  cudaGetSymbolAddress((void**)&vl,  g_vl);
    cudaGetSymbolAddress((void**)&oh,  g_oh);  cudaGetSymbolAddress((void**)&ol,  g_ol);

    cudaFuncSetAttribute(mma_gemm,
                         cudaFuncAttributeMaxDynamicSharedMemorySize, GK_SMEM);
    cudaFuncSetAttribute(qkv_gemm,
                         cudaFuncAttributeMaxDynamicSharedMemorySize, GK_SMEM);
    cudaFuncSetAttribute(flash_mma,
                         cudaFuncAttributeMaxDynamicSharedMemorySize, FLASH_SMEM);

    split5<<<dim3(NELEM / 4 / 256, 5), 256>>>(x, wq, wk, wv, wo,
        xh, xl, wqh, wql, wkh, wkl, wvh, wvl, woh, wol);

    adapter_gemv<<<128, 256>>>(adapter, wk, aKp);
    adapter_gemv<<<128, 256>>>(adapter, wv, aVp);

    qkv_gemm<<<dim3(DIM_ / 128, MROWS / 128, 3), 256, GK_SMEM>>>(
        xh, xl, wqh, wql, wkh, wkl, wvh, wvl,
        qh, ql, kh, kl, vh, vl, fcos, fsin);

    flash_mma<<<dim3(S_ / 128, H_, B_), 256, FLASH_SMEM>>>(
        qh, ql, kh, kl, vh, vl, aKp, aVp, gate, oh, ol);

    mma_gemm<<<dim3(DIM_ / 128, MROWS / 128), 256, GK_SMEM>>>(
        oh, ol, woh, wol, out);
}